// round 3
// baseline (speedup 1.0000x reference)
#include <cuda_runtime.h>
#include <math.h>

#define N_NODES 8192
#define N_EDGES 262144
#define IN_DIM  512
#define HID     128
#define ALPHA_C 0.5f
#define EOS_C   1e-10f
#define BIAS_C  1e-4f

// ---------------- scratch (static device memory; no allocations) ------------
#define TBITS 20
#define TSIZE (1u << TBITS)
#define TMASK (TSIZE - 1u)

struct Scratch {
    unsigned long long table[TSIZE];   // dedup hash: ((key+1)<<20) | edge_idx
    float deg_lp[N_NODES];
    float deg_hp[N_NODES];
    float inv_lp[N_NODES];
    float inv_hp[N_NODES];
    float c[N_NODES];
};
__device__ Scratch g_s;

__device__ __forceinline__ unsigned hash_key(unsigned key) {
    return (key * 2654435761u) >> 6 & TMASK;
}

__device__ __forceinline__ void table_insert(unsigned key, unsigned idx) {
    unsigned long long want = ((unsigned long long)(key + 1u) << 20) | idx;
    unsigned slot = hash_key(key);
    while (true) {
        unsigned long long cur = g_s.table[slot];
        if (cur == 0ull) {
            unsigned long long prev = atomicCAS(&g_s.table[slot], 0ull, want);
            if (prev == 0ull) return;
            cur = prev;
        }
        if ((cur >> 20) == (unsigned long long)(key + 1u)) {
            atomicMax(&g_s.table[slot], want);   // same key: max edge idx wins (last write)
            return;
        }
        slot = (slot + 1u) & TMASK;
    }
}

__device__ __forceinline__ unsigned table_lookup(unsigned key) {
    unsigned slot = hash_key(key);
    while (true) {
        unsigned long long cur = g_s.table[slot];
        if ((cur >> 20) == (unsigned long long)(key + 1u))
            return (unsigned)(cur & 0xFFFFFu);
        if (cur == 0ull) return 0xFFFFFFFFu;     // shouldn't happen
        slot = (slot + 1u) & TMASK;
    }
}

// ---------------- kernel 0: zero scratch (table + deg) ----------------------
__global__ void zero_scratch_kernel() {
    unsigned i = blockIdx.x * blockDim.x + threadIdx.x;
    if (i < TSIZE) g_s.table[i] = 0ull;
    if (i < N_NODES) { g_s.deg_lp[i] = 0.0f; g_s.deg_hp[i] = 0.0f; }
}

// ---------------- kernel 1: c[v] = relu(F[v]@W^T + b) . (Wa+Wb) -------------
// Tiled fp32 GEMM-reduce: 64 nodes/block, all 128 hidden, K chunks of 32.
#define BM 64
#define KC 32
__global__ __launch_bounds__(256) void node_score_kernel(
    const float* __restrict__ F, const float* __restrict__ W,
    const float* __restrict__ b_emb, const float* __restrict__ W_edge)
{
    __shared__ float Ws[KC][HID + 1];   // [k][h], padded vs bank conflicts
    __shared__ float Fs[BM][KC + 1];    // [m][k]

    int tid = threadIdx.x;
    int tx = tid & 15;        // hidden: h = tx + 16*j, j=0..7
    int ty = tid >> 4;        // nodes:  m = ty*4 + m4, m4=0..3
    int mbase = blockIdx.x * BM;

    float wsj[8], bj[8];
#pragma unroll
    for (int j = 0; j < 8; j++) {
        int h = tx + 16 * j;
        wsj[j] = W_edge[h] + W_edge[HID + h];
        bj[j]  = b_emb[h];
    }

    float acc[4][8];
#pragma unroll
    for (int m = 0; m < 4; m++)
#pragma unroll
        for (int j = 0; j < 8; j++) acc[m][j] = 0.0f;

    for (int k0 = 0; k0 < IN_DIM; k0 += KC) {
#pragma unroll
        for (int e = tid; e < KC * HID; e += 256) {      // 16 iters, coalesced
            int h = e >> 5, k = e & 31;
            Ws[k][h] = W[h * IN_DIM + k0 + k];
        }
#pragma unroll
        for (int e = tid; e < BM * KC; e += 256) {       // 8 iters, coalesced
            int m = e >> 5, k = e & 31;
            Fs[m][k] = F[(size_t)(mbase + m) * IN_DIM + k0 + k];
        }
        __syncthreads();

#pragma unroll
        for (int k = 0; k < KC; k++) {
            float wr[8];
#pragma unroll
            for (int j = 0; j < 8; j++) wr[j] = Ws[k][tx + 16 * j];
#pragma unroll
            for (int m = 0; m < 4; m++) {
                float f = Fs[ty * 4 + m][k];
#pragma unroll
                for (int j = 0; j < 8; j++) acc[m][j] += f * wr[j];
            }
        }
        __syncthreads();
    }

    // epilogue: relu, dot with (Wa+Wb), reduce across the 16 tx lanes
#pragma unroll
    for (int m = 0; m < 4; m++) {
        float p = 0.0f;
#pragma unroll
        for (int j = 0; j < 8; j++) {
            float h = acc[m][j] + bj[j];
            if (h > 0.0f) p += h * wsj[j];
        }
#pragma unroll
        for (int s = 8; s > 0; s >>= 1)
            p += __shfl_xor_sync(0xFFFFFFFFu, p, s, 16);
        if (tx == 0) g_s.c[mbase + ty * 4 + m] = p;
    }
}

// ---------------- kernel 2: per-edge gate weights + hash insert -------------
__global__ __launch_bounds__(256) void edge_pass1_kernel(
    const int* __restrict__ edges, const float* __restrict__ noise,
    const float* __restrict__ b_edge,
    float* __restrict__ wlp_out, float* __restrict__ whp_out)
{
    int i = blockIdx.x * blockDim.x + threadIdx.x;
    if (i >= N_EDGES) return;
    int e0 = edges[i];
    int e1 = edges[N_EDGES + i];
    float raw = 0.5f * (g_s.c[e0] + g_s.c[e1]) + b_edge[0];
    float eps = (BIAS_C - (1.0f - BIAS_C)) * noise[i] + (1.0f - BIAS_C);
    float gate = logf(eps) - log1pf(-eps) + raw;          // TEMPERATURE = 1
    float wlp = 1.0f / (1.0f + expf(-gate));
    wlp_out[i] = wlp;
    whp_out[i] = 1.0f - wlp;

    unsigned key = (unsigned)e0 * (unsigned)N_NODES + (unsigned)e1;
    table_insert(key, (unsigned)i);
}

// ---------------- kernel 3: winners accumulate degrees ----------------------
__global__ __launch_bounds__(256) void edge_pass2_kernel(
    const int* __restrict__ edges,
    const float* __restrict__ wlp, const float* __restrict__ whp)
{
    int i = blockIdx.x * blockDim.x + threadIdx.x;
    if (i >= N_EDGES) return;
    int e0 = edges[i];
    int e1 = edges[N_EDGES + i];
    unsigned key = (unsigned)e0 * (unsigned)N_NODES + (unsigned)e1;
    if (table_lookup(key) == (unsigned)i) {
        atomicAdd(&g_s.deg_lp[e0], wlp[i]);
        atomicAdd(&g_s.deg_hp[e0], whp[i]);
    }
}

// ---------------- kernel 4: inv_sqrt_deg + diagonal writes ------------------
__global__ __launch_bounds__(256) void inv_diag_kernel(
    float* __restrict__ adj_lp, float* __restrict__ adj_hp)
{
    int i = blockIdx.x * blockDim.x + threadIdx.x;
    if (i >= N_NODES) return;
    float il = 1.0f / (sqrtf(g_s.deg_lp[i] + 1.0f) + EOS_C);
    float ih = 1.0f / (sqrtf(g_s.deg_hp[i] + 1.0f) + EOS_C);
    g_s.inv_lp[i] = il;
    g_s.inv_hp[i] = ih;
    size_t d = (size_t)i * N_NODES + i;
    adj_lp[d] = il * il;   // eye entry, normalized (overwritten if self-edge)
    adj_hp[d] = 1.0f;      // mask kills the normalized part on the diagonal
}

// ---------------- kernel 5: scatter final normalized values -----------------
__global__ __launch_bounds__(256) void scatter_kernel(
    const int* __restrict__ edges,
    const float* __restrict__ wlp_a, const float* __restrict__ whp_a,
    float* __restrict__ adj_lp, float* __restrict__ adj_hp)
{
    int i = blockIdx.x * blockDim.x + threadIdx.x;
    if (i >= N_EDGES) return;
    int e0 = edges[i];
    int e1 = edges[N_EDGES + i];
    unsigned key = (unsigned)e0 * (unsigned)N_NODES + (unsigned)e1;
    if (table_lookup(key) != (unsigned)i) return;   // only dedup winner writes

    float wlp = wlp_a[i];
    float whp = whp_a[i];
    float il = g_s.inv_lp[e0] * g_s.inv_lp[e1];
    float ih = g_s.inv_hp[e0] * g_s.inv_hp[e1];
    size_t off = (size_t)e0 * N_NODES + e1;
    if (e0 == e1) {
        adj_lp[off] = (wlp + 1.0f) * il;                    // scatter + eye, normalized
        adj_hp[off] = 1.0f - ALPHA_C * (whp + 1.0f) * ih;   // eye - norm*mask*alpha
    } else {
        adj_lp[off] = wlp * il;
        adj_hp[off] = -ALPHA_C * whp * ih;
    }
}

// ---------------- launch -----------------------------------------------------
extern "C" void kernel_launch(void* const* d_in, const int* in_sizes, int n_in,
                              void* d_out, int out_size)
{
    const float* F      = (const float*)d_in[0];
    const float* W      = (const float*)d_in[1];
    const float* b_emb  = (const float*)d_in[2];
    const float* W_edge = (const float*)d_in[3];
    const float* b_edge = (const float*)d_in[4];
    const float* noise  = (const float*)d_in[5];
    const int*   edges  = (const int*)d_in[6];

    float* out    = (float*)d_out;
    float* adj_lp = out;
    float* adj_hp = out + (size_t)N_NODES * N_NODES;
    float* wlp    = out + 2ull * N_NODES * N_NODES;
    float* whp    = wlp + N_EDGES;

    // zero both adjacency matrices (bulk of the traffic: 537 MB write)
    cudaMemsetAsync(d_out, 0, 2ull * N_NODES * N_NODES * sizeof(float), 0);

    zero_scratch_kernel<<<(TSIZE + 255) / 256, 256>>>();
    node_score_kernel<<<N_NODES / BM, 256>>>(F, W, b_emb, W_edge);
    edge_pass1_kernel<<<N_EDGES / 256, 256>>>(edges, noise, b_edge, wlp, whp);
    edge_pass2_kernel<<<N_EDGES / 256, 256>>>(edges, wlp, whp);
    inv_diag_kernel<<<N_NODES / 256, 256>>>(adj_lp, adj_hp);
    scatter_kernel<<<N_EDGES / 256, 256>>>(edges, wlp, whp, adj_lp, adj_hp);
}

// round 8
// speedup vs baseline: 1.2300x; 1.2300x over previous
#include <cuda_runtime.h>
#include <math.h>

#define N_NODES 8192
#define N_EDGES 262144
#define IN_DIM  512
#define HID     128
#define ALPHA_C 0.5f
#define EOS_C   1e-10f
#define BIAS_C  1e-4f

// ---------------- scratch (static device memory; no allocations) ------------
#define TBITS 20
#define TSIZE (1u << TBITS)
#define TMASK (TSIZE - 1u)

struct Scratch {
    unsigned long long table[TSIZE];   // dedup hash: ((key+1)<<20) | edge_idx
    float deg_lp[N_NODES];
    float deg_hp[N_NODES];
    float inv_lp[N_NODES];
    float inv_hp[N_NODES];
    float c[N_NODES];
};
__device__ Scratch g_s;

// zero-chunk work queues + grid barrier state (module-load zeroed; each phase
// that consumes a counter is followed by a reset before kernel exit, so every
// graph replay starts from the same state).
__device__ unsigned g_ctrA;
__device__ unsigned g_ctrB;
__device__ unsigned g_bar_cnt;
__device__ volatile unsigned g_bar_gen;

// ---------------- dedup hash -------------------------------------------------
__device__ __forceinline__ unsigned hash_key(unsigned key) {
    return (key * 2654435761u) >> 6 & TMASK;
}

__device__ __forceinline__ void table_insert(unsigned key, unsigned idx) {
    unsigned long long want = ((unsigned long long)(key + 1u) << 20) | idx;
    unsigned slot = hash_key(key);
    while (true) {
        unsigned long long cur = g_s.table[slot];
        if (cur == 0ull) {
            unsigned long long prev = atomicCAS(&g_s.table[slot], 0ull, want);
            if (prev == 0ull) return;
            cur = prev;
        }
        if ((cur >> 20) == (unsigned long long)(key + 1u)) {
            atomicMax(&g_s.table[slot], want);   // same key: max edge idx wins
            return;
        }
        slot = (slot + 1u) & TMASK;
    }
}

__device__ __forceinline__ unsigned table_lookup(unsigned key) {
    unsigned slot = hash_key(key);
    while (true) {
        unsigned long long cur = g_s.table[slot];
        if ((cur >> 20) == (unsigned long long)(key + 1u))
            return (unsigned)(cur & 0xFFFFFu);
        if (cur == 0ull) return 0xFFFFFFFFu;
        slot = (slot + 1u) & TMASK;
    }
}

// ---------------- software grid barrier (grid sized for co-residency) --------
__device__ __forceinline__ void grid_bar() {
    __syncthreads();
    if (threadIdx.x == 0) {
        __threadfence();                       // publish this block's writes
        unsigned gen = g_bar_gen;
        if (atomicAdd(&g_bar_cnt, 1u) == gridDim.x - 1u) {
            g_bar_cnt = 0u;
            __threadfence();
            g_bar_gen = gen + 1u;              // release
        } else {
            while (g_bar_gen == gen) __nanosleep(64);
        }
        __threadfence();                       // acquire
    }
    __syncthreads();
}

// ---------------- adjacency zero chunks --------------------------------------
#define CHUNK_LOG 15                            // 32768 float4 = 512 KB / chunk
#define CHUNK_F4  (1u << CHUNK_LOG)
#define ADJ_F4    (2ull * N_NODES * N_NODES / 4)        // 33,554,432 float4
#define NCHUNKS   ((unsigned)(ADJ_F4 >> CHUNK_LOG))     // 1024
#define LIMIT_A   (NCHUNKS - 192u)              // defer 96 MB into phase B

__device__ __forceinline__ void zero_chunk(float4* adj, unsigned c) {
    float4* p = adj + ((size_t)c << CHUNK_LOG);
    const float4 z = make_float4(0.f, 0.f, 0.f, 0.f);
#pragma unroll 4
    for (unsigned i = threadIdx.x; i < CHUNK_F4; i += 256u) p[i] = z;
}

// ---------------- node score tile: c[v] = relu(F[v]@W^T + b) . (Wa+Wb) -------
#define BM 64
#define KC 32

// ---------------- single fused persistent kernel -----------------------------
__global__ __launch_bounds__(256) void fused_kernel(
    const float* __restrict__ F, const float* __restrict__ W,
    const float* __restrict__ b_emb, const float* __restrict__ W_edge,
    const float* __restrict__ b_edge, const float* __restrict__ noise,
    const int* __restrict__ edges,
    float* __restrict__ adj_lp, float* __restrict__ adj_hp,
    float* __restrict__ wlp, float* __restrict__ whp)
{
    __shared__ float Ws[KC][HID + 1];
    __shared__ float Fs[BM][KC + 1];

    const int tid = threadIdx.x;
    const unsigned gthreads = gridDim.x * 256u;
    const unsigned gid = blockIdx.x * 256u + tid;
    float4* adj4 = (float4*)adj_lp;             // lp followed by hp, contiguous

    // ===================== Phase A ==========================================
    // (a) zero dedup table + degree accumulators (grid-stride, 8 MB)
    for (unsigned i = gid; i < TSIZE; i += gthreads) g_s.table[i] = 0ull;
    for (unsigned i = gid; i < N_NODES; i += gthreads) {
        g_s.deg_lp[i] = 0.0f;
        g_s.deg_hp[i] = 0.0f;
    }

    // (b) node scores: 128 tiles of 64 nodes
    for (unsigned t = blockIdx.x; t < N_NODES / BM; t += gridDim.x) {
        const int tx = tid & 15;     // hidden lane: h = tx + 16*j
        const int ty = tid >> 4;     // node group
        const int mbase = t * BM;

        float wsj[8], bj[8];
#pragma unroll
        for (int j = 0; j < 8; j++) {
            int h = tx + 16 * j;
            wsj[j] = W_edge[h] + W_edge[HID + h];
            bj[j]  = b_emb[h];
        }

        float acc[4][8];
#pragma unroll
        for (int m = 0; m < 4; m++)
#pragma unroll
            for (int j = 0; j < 8; j++) acc[m][j] = 0.0f;

        for (int k0 = 0; k0 < IN_DIM; k0 += KC) {
#pragma unroll
            for (int e = tid; e < KC * HID; e += 256) {
                int h = e >> 5, k = e & 31;
                Ws[k][h] = W[h * IN_DIM + k0 + k];
            }
#pragma unroll
            for (int e = tid; e < BM * KC; e += 256) {
                int m = e >> 5, k = e & 31;
                Fs[m][k] = F[(size_t)(mbase + m) * IN_DIM + k0 + k];
            }
            __syncthreads();

#pragma unroll
            for (int k = 0; k < KC; k++) {
                float wr[8];
#pragma unroll
                for (int j = 0; j < 8; j++) wr[j] = Ws[k][tx + 16 * j];
#pragma unroll
                for (int m = 0; m < 4; m++) {
                    float f = Fs[ty * 4 + m][k];
#pragma unroll
                    for (int j = 0; j < 8; j++) acc[m][j] += f * wr[j];
                }
            }
            __syncthreads();
        }

#pragma unroll
        for (int m = 0; m < 4; m++) {
            float p = 0.0f;
#pragma unroll
            for (int j = 0; j < 8; j++) {
                float h = acc[m][j] + bj[j];
                if (h > 0.0f) p += h * wsj[j];
            }
#pragma unroll
            for (int s = 8; s > 0; s >>= 1)
                p += __shfl_xor_sync(0xFFFFFFFFu, p, s, 16);
            if (tx == 0) g_s.c[mbase + ty * 4 + m] = p;
        }
    }

    // (c) drain adjacency zero chunks [0, LIMIT_A) — the DRAM-write phase that
    //     hides (a) and (b)
    for (;;) {
        unsigned t;
        if (tid == 0) t = atomicAdd(&g_ctrA, 1u);
        t = __shfl_sync(0xFFFFFFFFu, t, 0);     // broadcast within warp...
        __shared__ unsigned s_t;
        if (tid == 0) s_t = t;
        __syncthreads();
        t = s_t;
        __syncthreads();
        if (t >= LIMIT_A) break;
        zero_chunk(adj4, t);
    }

    grid_bar();   // scores + table ready

    // ===================== Phase B: gate weights + hash insert ===============
    for (unsigned i = gid; i < N_EDGES; i += gthreads) {
        int e0 = edges[i];
        int e1 = edges[N_EDGES + i];
        float raw = 0.5f * (g_s.c[e0] + g_s.c[e1]) + b_edge[0];
        float eps = (BIAS_C - (1.0f - BIAS_C)) * noise[i] + (1.0f - BIAS_C);
        float gate = logf(eps) - log1pf(-eps) + raw;     // TEMPERATURE = 1
        float w = 1.0f / (1.0f + expf(-gate));
        wlp[i] = w;
        whp[i] = 1.0f - w;
        table_insert((unsigned)e0 * (unsigned)N_NODES + (unsigned)e1, i);
    }
    // drain remaining zero chunks [LIMIT_A, NCHUNKS) — overlaps pass-1 latency
    for (;;) {
        __shared__ unsigned s_t2;
        if (tid == 0) s_t2 = atomicAdd(&g_ctrB, 1u);
        __syncthreads();
        unsigned t = s_t2;
        __syncthreads();
        if (t >= NCHUNKS - LIMIT_A) break;
        zero_chunk(adj4, LIMIT_A + t);
    }

    grid_bar();   // inserts + full adjacency zero complete

    // ===================== Phase C: winners accumulate degrees ===============
    for (unsigned i = gid; i < N_EDGES; i += gthreads) {
        int e0 = edges[i];
        int e1 = edges[N_EDGES + i];
        unsigned key = (unsigned)e0 * (unsigned)N_NODES + (unsigned)e1;
        if (table_lookup(key) == i) {
            atomicAdd(&g_s.deg_lp[e0], wlp[i]);
            atomicAdd(&g_s.deg_hp[e0], whp[i]);
        }
    }

    grid_bar();   // degrees complete

    // ===================== Phase D: inv-sqrt + diagonal ======================
    if (gid == 0) { g_ctrA = 0u; g_ctrB = 0u; }   // reset queues for next replay
    for (unsigned i = gid; i < N_NODES; i += gthreads) {
        float il = 1.0f / (sqrtf(g_s.deg_lp[i] + 1.0f) + EOS_C);
        float ih = 1.0f / (sqrtf(g_s.deg_hp[i] + 1.0f) + EOS_C);
        g_s.inv_lp[i] = il;
        g_s.inv_hp[i] = ih;
        size_t d = (size_t)i * N_NODES + i;
        adj_lp[d] = il * il;   // normalized eye entry (overwritten if self-edge)
        adj_hp[d] = 1.0f;      // mask kills normalized part off the edge set
    }

    grid_bar();   // inv tables + diagonals ready

    // ===================== Phase E: scatter final normalized values ==========
    for (unsigned i = gid; i < N_EDGES; i += gthreads) {
        int e0 = edges[i];
        int e1 = edges[N_EDGES + i];
        unsigned key = (unsigned)e0 * (unsigned)N_NODES + (unsigned)e1;
        if (table_lookup(key) != i) continue;    // only dedup winner writes

        float w_lp = wlp[i];
        float w_hp = whp[i];
        float il = g_s.inv_lp[e0] * g_s.inv_lp[e1];
        float ih = g_s.inv_hp[e0] * g_s.inv_hp[e1];
        size_t off = (size_t)e0 * N_NODES + e1;
        if (e0 == e1) {
            adj_lp[off] = (w_lp + 1.0f) * il;
            adj_hp[off] = 1.0f - ALPHA_C * (w_hp + 1.0f) * ih;
        } else {
            adj_lp[off] = w_lp * il;
            adj_hp[off] = -ALPHA_C * w_hp * ih;
        }
    }
}

// ---------------- launch -----------------------------------------------------
extern "C" void kernel_launch(void* const* d_in, const int* in_sizes, int n_in,
                              void* d_out, int out_size)
{
    const float* F      = (const float*)d_in[0];
    const float* W      = (const float*)d_in[1];
    const float* b_emb  = (const float*)d_in[2];
    const float* W_edge = (const float*)d_in[3];
    const float* b_edge = (const float*)d_in[4];
    const float* noise  = (const float*)d_in[5];
    const int*   edges  = (const int*)d_in[6];

    float* out    = (float*)d_out;
    float* adj_lp = out;
    float* adj_hp = out + (size_t)N_NODES * N_NODES;
    float* wlp    = out + 2ull * N_NODES * N_NODES;
    float* whp    = wlp + N_EDGES;

    // size the persistent grid for guaranteed co-residency (software barrier)
    int dev = 0;
    cudaGetDevice(&dev);
    int sms = 0;
    cudaDeviceGetAttribute(&sms, cudaDevAttrMultiProcessorCount, dev);
    int per_sm = 0;
    cudaOccupancyMaxActiveBlocksPerMultiprocessor(&per_sm, fused_kernel, 256, 0);
    if (per_sm < 1) per_sm = 1;
    if (per_sm > 2) per_sm = 2;
    int nb = sms * per_sm;

    fused_kernel<<<nb, 256>>>(F, W, b_emb, W_edge, b_edge, noise, edges,
                              adj_lp, adj_hp, wlp, whp);
}